// round 4
// baseline (speedup 1.0000x reference)
#include <cuda_runtime.h>
#include <math.h>

// ---------------------------------------------------------------------------
// Problem constants
// ---------------------------------------------------------------------------
#define TTS   21      // Tm = CAP-1 decode steps
#define CAPL  22
#define BBS   128     // batch
#define PPS   196     // pixels
#define ENCD  2048
#define DHID  1024
#define VOC   32000

static constexpr long long O_PRED = 0;
static constexpr long long O_CAPS = (long long)BBS * TTS * VOC;   // 86,016,000
static constexpr long long O_DECL = O_CAPS + (long long)BBS * CAPL;
static constexpr long long O_SORT = O_DECL + BBS;
static constexpr long long O_RPOS = O_SORT + BBS;
static constexpr long long O_PPOS = O_RPOS + (long long)BBS * TTS;

// ---------------------------------------------------------------------------
// Static device scratch (no runtime allocation allowed)
// ---------------------------------------------------------------------------
__device__ float d_encs [(size_t)BBS * PPS * ENCD];   // sorted encoder (205.5 MB)
__device__ float d_att1 [(size_t)BBS * PPS * DHID];   // att1 (102.8 MB)
__device__ float d_econ [(size_t)TTS * BBS * 4 * DHID]; // embed @ Wih_e^T (44 MB)
__device__ float d_embg [(size_t)TTS * BBS * DHID];   // gathered embeddings
__device__ float d_W1cat[4096 * 2048];                // [Wih(:,1024:2048) | Whh]
__device__ float d_W2cat[(size_t)4096 * 4096];        // [l2_Wih | l2_Whh]
__device__ float d_W3cat[3072 * 1024];                // [dec_att_W ; f_beta_W]
__device__ float d_b1sum[4096];
__device__ float d_b2sum[4096];
__device__ float d_b3cat[3072];
__device__ float d_base1[BBS * 4096];                 // biases + mean_enc contrib
__device__ float d_gates[BBS * 4096];
__device__ float d_x1   [BBS * 2048];                 // [h2_state | h1_state]
__device__ float d_x2   [BBS * 4096];                 // [att | h1n | h2_state]
__device__ float d_ag   [BBS * 3072];                 // [att2 | gate logits]
__device__ float d_c1   [BBS * DHID];
__device__ float d_c2   [BBS * DHID];
__device__ float d_mean [BBS * ENCD];
__device__ float d_h2all[(size_t)TTS * BBS * DHID];   // unmasked h2n candidates
__device__ int   d_sort  [BBS];
__device__ int   d_declen[BBS];
__device__ int   d_tokens[TTS * BBS];

// ---------------------------------------------------------------------------
// Math helpers
// ---------------------------------------------------------------------------
__device__ __forceinline__ float sigf(float x) {
    return 1.0f / (1.0f + __expf(-x));
}
__device__ __forceinline__ float tanh_fast(float x) {
    // 1 - 2/(e^{2x}+1); saturates correctly at +-1 for large |x|
    return 1.0f - 2.0f / (__expf(2.0f * x) + 1.0f);
}

// ---------------------------------------------------------------------------
// Setup: stable descending argsort of lengths; caps/dec_len/sort/rel_pos out
// ---------------------------------------------------------------------------
__global__ void setup_kernel(const int* __restrict__ caplen,
                             const int* __restrict__ caps,
                             float* __restrict__ out) {
    __shared__ int lens_s[BBS];
    __shared__ int sort_s[BBS];
    int i = threadIdx.x;
    int li = caplen[i];
    lens_s[i] = li;
    __syncthreads();
    int rank = 0;
    for (int j = 0; j < BBS; ++j) {
        int lj = lens_s[j];
        if (lj > li || (lj == li && j < i)) rank++;
    }
    sort_s[rank] = i;
    __syncthreads();
    int src = sort_s[i];
    d_sort[i] = src;
    int dl = lens_s[src] - 1;
    d_declen[i] = dl;
    out[O_DECL + i] = (float)dl;
    out[O_SORT + i] = (float)src;
    for (int t = 0; t < CAPL; ++t) {
        int tok = caps[src * CAPL + t];
        out[O_CAPS + (long long)i * CAPL + t] = (float)tok;
        if (t < TTS) d_tokens[t * BBS + i] = tok;
    }
    float dlf = (float)dl;
    for (int s = 0; s < TTS; ++s)
        out[O_RPOS + (long long)i * TTS + s] =
            (s < dl) ? ((float)(s + 1) / dlf) : 0.0f;
}

// ---------------------------------------------------------------------------
// Gather sorted encoder rows (float4), 50176 blocks x 256
// ---------------------------------------------------------------------------
__global__ void gather_enc_kernel(const float* __restrict__ enc) {
    int g = blockIdx.x * 256 + threadIdx.x;          // float4 index
    const int V4ROW = ENCD / 4;                      // 512
    int r = g / V4ROW;                               // sorted row 0..25087
    int w = g % V4ROW;
    int b = r / PPS, p = r % PPS;
    int srow = d_sort[b] * PPS + p;
    const float4* src = (const float4*)enc;
    float4* dst = (float4*)d_encs;
    dst[(size_t)r * V4ROW + w] = src[(size_t)srow * V4ROW + w];
}

// ---------------------------------------------------------------------------
// mean over pixels: one thread per (b,e)
// ---------------------------------------------------------------------------
__global__ void mean_kernel() {
    int idx = blockIdx.x * 256 + threadIdx.x;        // 0 .. 128*2048
    int b = idx / ENCD, e = idx % ENCD;
    const float* base = d_encs + (size_t)b * PPS * ENCD + e;
    float s = 0.f;
    #pragma unroll 4
    for (int p = 0; p < PPS; ++p) s += base[(size_t)p * ENCD];
    d_mean[idx] = s * (1.0f / (float)PPS);
}

// ---------------------------------------------------------------------------
// Weight concatenation copies (float4) + bias sums
// ---------------------------------------------------------------------------
__global__ void w1copy_kernel(const float* __restrict__ l1Wih,
                              const float* __restrict__ l1Whh) {
    int g = blockIdx.x * 256 + threadIdx.x;          // float4 over 4096x2048
    int j = g / (2048 / 4);
    int c4 = g % (2048 / 4);
    int c = c4 * 4;
    float4 v;
    if (c < 1024) v = *(const float4*)(l1Wih + (size_t)j * 4096 + 1024 + c);
    else          v = *(const float4*)(l1Whh + (size_t)j * 1024 + (c - 1024));
    *(float4*)(d_W1cat + (size_t)j * 2048 + c) = v;
}

__global__ void w2copy_kernel(const float* __restrict__ l2Wih,
                              const float* __restrict__ l2Whh) {
    int g = blockIdx.x * 256 + threadIdx.x;          // float4 over 4096x4096
    int j = g / (4096 / 4);
    int c = (g % (4096 / 4)) * 4;
    float4 v;
    if (c < 3072) v = *(const float4*)(l2Wih + (size_t)j * 3072 + c);
    else          v = *(const float4*)(l2Whh + (size_t)j * 1024 + (c - 3072));
    *(float4*)(d_W2cat + (size_t)j * 4096 + c) = v;
}

__global__ void w3copy_kernel(const float* __restrict__ daW,
                              const float* __restrict__ fbW) {
    int g = blockIdx.x * 256 + threadIdx.x;          // float4 over 3072x1024
    int j = g / (1024 / 4);
    int c = (g % (1024 / 4)) * 4;
    float4 v;
    if (j < 1024) v = *(const float4*)(daW + (size_t)j * 1024 + c);
    else          v = *(const float4*)(fbW + (size_t)(j - 1024) * 1024 + c);
    *(float4*)(d_W3cat + (size_t)j * 1024 + c) = v;
}

__global__ void bias_kernel(const float* __restrict__ l1bih,
                            const float* __restrict__ l1bhh,
                            const float* __restrict__ l2bih,
                            const float* __restrict__ l2bhh,
                            const float* __restrict__ dab,
                            const float* __restrict__ fbb) {
    int j = blockIdx.x * 256 + threadIdx.x;          // 0..4095
    d_b1sum[j] = l1bih[j] + l1bhh[j];
    d_b2sum[j] = l2bih[j] + l2bhh[j];
    if (j < 3072) d_b3cat[j] = (j < 1024) ? dab[j] : fbb[j - 1024];
}

// ---------------------------------------------------------------------------
// Gather token embeddings: one block per row (t*128+b)
// ---------------------------------------------------------------------------
__global__ void embg_kernel(const float* __restrict__ emb) {
    int m = blockIdx.x;
    int tok = d_tokens[m];
    const float4* src = (const float4*)(emb + (size_t)tok * DHID);
    float4* dst = (float4*)(d_embg + (size_t)m * DHID);
    dst[threadIdx.x] = src[threadIdx.x];
}

// ---------------------------------------------------------------------------
// Zero initial states
// ---------------------------------------------------------------------------
__global__ void zero_kernel() {
    int idx = blockIdx.x * 256 + threadIdx.x;        // 0 .. 524287
    d_x2[idx] = 0.f;
    if (idx < BBS * 2048) d_x1[idx] = 0.f;
    if (idx < BBS * DHID) { d_c1[idx] = 0.f; d_c2[idx] = 0.f; }
}

// ---------------------------------------------------------------------------
// GEMM: C[m,n] = sum_k A[m,k]*B[n,k] (+bias[n]) (+add0[m,n]) (+add1[m,n])
// All dims divisible by tile sizes (verified for every call site).
// BM x BN tile, BK=16, 256 threads, TM x TN micro-tile per thread.
// PRED variant: permuted masked store into predictions output.
// ---------------------------------------------------------------------------
template<int BM, int BN, int TM, int TN, bool BIAS, int NADD, bool PRED>
__global__ void gemm_tn(const float* __restrict__ A,
                        const float* __restrict__ Bm,
                        const float* __restrict__ bias,
                        const float* __restrict__ add0,
                        const float* __restrict__ add1,
                        float* __restrict__ C,
                        int N, int K, int lda, int ldb, int ldc) {
    const int BK = 16;
    __shared__ float As[BK][BM + 4];
    __shared__ float Bs[BK][BN + 4];
    const int tid = threadIdx.x;
    const int NT = BN / TN;                // threads along n
    const int tx = tid % NT;
    const int ty = tid / NT;               // 0 .. BM/TM-1
    const int m0 = blockIdx.y * BM;
    const int n0 = blockIdx.x * BN;

    float acc[TM][TN];
    #pragma unroll
    for (int i = 0; i < TM; ++i)
        #pragma unroll
        for (int j = 0; j < TN; ++j) acc[i][j] = 0.f;

    for (int k0 = 0; k0 < K; k0 += BK) {
        #pragma unroll
        for (int i = tid; i < BM * BK; i += 256) {
            int m = i / BK, k = i % BK;
            As[k][m] = A[(size_t)(m0 + m) * lda + k0 + k];
        }
        #pragma unroll
        for (int i = tid; i < BN * BK; i += 256) {
            int n = i / BK, k = i % BK;
            Bs[k][n] = Bm[(size_t)(n0 + n) * ldb + k0 + k];
        }
        __syncthreads();
        #pragma unroll
        for (int kk = 0; kk < BK; ++kk) {
            float a[TM], b[TN];
            #pragma unroll
            for (int i = 0; i < TM; ++i) a[i] = As[kk][ty * TM + i];
            #pragma unroll
            for (int j = 0; j < TN; ++j) b[j] = Bs[kk][tx * TN + j];
            #pragma unroll
            for (int i = 0; i < TM; ++i)
                #pragma unroll
                for (int j = 0; j < TN; ++j)
                    acc[i][j] = fmaf(a[i], b[j], acc[i][j]);
        }
        __syncthreads();
    }

    #pragma unroll
    for (int i = 0; i < TM; ++i) {
        int m = m0 + ty * TM + i;
        #pragma unroll
        for (int j = 0; j < TN; ++j) {
            int n = n0 + tx * TN + j;
            float v = acc[i][j];
            if (BIAS)      v += bias[n];
            if (NADD >= 1) v += add0[(size_t)m * ldc + n];
            if (NADD >= 2) v += add1[(size_t)m * ldc + n];
            if (PRED) {
                int t = m / BBS, b = m % BBS;
                long long row = (long long)b * TTS + t;
                C[row * (long long)N + n] = (t < d_declen[b]) ? v : 0.f;
            } else {
                C[(size_t)m * ldc + n] = v;
            }
        }
    }
}

// ---------------------------------------------------------------------------
// LSTM pointwise kernels (gate order: i, f, g, o)
// ---------------------------------------------------------------------------
__global__ void lstm1_kernel(int t) {
    int idx = blockIdx.x * 256 + threadIdx.x;        // 0 .. 128*1024
    int b = idx / DHID, k = idx % DHID;
    const float* g = d_gates + (size_t)b * 4096;
    float ig = g[k], fg = g[1024 + k], gg = g[2048 + k], og = g[3072 + k];
    float c = d_c1[idx];
    float cn = sigf(fg) * c + sigf(ig) * tanhf(gg);
    float hn = sigf(og) * tanhf(cn);
    d_x2[(size_t)b * 4096 + 2048 + k] = hn;          // candidate h1n (unmasked)
    if (t < d_declen[b]) {
        d_c1[idx] = cn;
        d_x1[(size_t)b * 2048 + 1024 + k] = hn;      // carried h1 state
    }
}

__global__ void lstm2_kernel(int t) {
    int idx = blockIdx.x * 256 + threadIdx.x;
    int b = idx / DHID, k = idx % DHID;
    const float* g = d_gates + (size_t)b * 4096;
    float ig = g[k], fg = g[1024 + k], gg = g[2048 + k], og = g[3072 + k];
    float c = d_c2[idx];
    float cn = sigf(fg) * c + sigf(ig) * tanhf(gg);
    float hn = sigf(og) * tanhf(cn);
    d_h2all[(size_t)(t * BBS + b) * DHID + k] = hn;  // candidate (unmasked)
    if (t < d_declen[b]) {
        d_c2[idx] = cn;
        d_x1[(size_t)b * 2048 + k] = hn;             // carried h2 state
        d_x2[(size_t)b * 4096 + 3072 + k] = hn;
    }
}

// ---------------------------------------------------------------------------
// Fused attention: scores = tanh(att1 + att2) . w + b0; softmax over p;
// awe = alpha @ enc; x2.att = sigmoid(gate_logits) * awe.   One block per b.
// ---------------------------------------------------------------------------
__global__ void attn_kernel(const float* __restrict__ fullW,
                            const float* __restrict__ fullb) {
    __shared__ float s_a2[DHID];
    __shared__ float s_w [DHID];
    __shared__ float s_sc[PPS];
    __shared__ float s_red[256];
    const int b = blockIdx.x;
    const int tid = threadIdx.x;
    const int lane = tid & 31, warp = tid >> 5;

    for (int i = tid; i < DHID; i += 256) {
        s_a2[i] = d_ag[(size_t)b * 3072 + i];
        s_w[i]  = fullW[i];
    }
    __syncthreads();

    const float b0 = fullb[0];
    for (int p = warp; p < PPS; p += 8) {
        const float* row = d_att1 + ((size_t)b * PPS + p) * DHID;
        float s = 0.f;
        #pragma unroll 8
        for (int a = lane; a < DHID; a += 32)
            s += tanh_fast(row[a] + s_a2[a]) * s_w[a];
        #pragma unroll
        for (int o = 16; o > 0; o >>= 1)
            s += __shfl_down_sync(0xffffffffu, s, o);
        if (lane == 0) s_sc[p] = s + b0;
    }
    __syncthreads();

    // softmax over 196
    s_red[tid] = (tid < PPS) ? s_sc[tid] : -INFINITY;
    __syncthreads();
    for (int s = 128; s > 0; s >>= 1) {
        if (tid < s) s_red[tid] = fmaxf(s_red[tid], s_red[tid + s]);
        __syncthreads();
    }
    float mx = s_red[0];
    __syncthreads();
    float e = 0.f;
    if (tid < PPS) { e = __expf(s_sc[tid] - mx); }
    s_red[tid] = e;
    __syncthreads();
    for (int s = 128; s > 0; s >>= 1) {
        if (tid < s) s_red[tid] += s_red[tid + s];
        __syncthreads();
    }
    float inv = 1.0f / s_red[0];
    __syncthreads();
    if (tid < PPS) s_sc[tid] = e * inv;              // alpha
    __syncthreads();

    // awe + gate
    const float* encb = d_encs + (size_t)b * PPS * ENCD;
    for (int ei = tid; ei < ENCD; ei += 256) {
        float acc = 0.f;
        const float* col = encb + ei;
        #pragma unroll 4
        for (int p = 0; p < PPS; ++p)
            acc = fmaf(s_sc[p], col[(size_t)p * ENCD], acc);
        float gate = sigf(d_ag[(size_t)b * 3072 + 1024 + ei]);
        d_x2[(size_t)b * 4096 + ei] = gate * acc;
    }
}

// ---------------------------------------------------------------------------
// predicted_pos: one warp per (t,b) row
// ---------------------------------------------------------------------------
__global__ void rpm_kernel(const float* __restrict__ rpmW,
                           float* __restrict__ out) {
    int m = blockIdx.x * 8 + (threadIdx.x >> 5);
    if (m >= TTS * BBS) return;
    int lane = threadIdx.x & 31;
    int t = m / BBS, b = m % BBS;
    const float* h = d_h2all + (size_t)m * DHID;
    float s = 0.f;
    #pragma unroll 8
    for (int k = lane; k < DHID; k += 32) s += h[k] * rpmW[k];
    #pragma unroll
    for (int o = 16; o > 0; o >>= 1)
        s += __shfl_down_sync(0xffffffffu, s, o);
    if (lane == 0)
        out[O_PPOS + (long long)b * TTS + t] =
            (t < d_declen[b]) ? sigf(s) : 0.f;
}

// ---------------------------------------------------------------------------
// Launch
// ---------------------------------------------------------------------------
extern "C" void kernel_launch(void* const* d_in, const int* in_sizes, int n_in,
                              void* d_out, int out_size) {
    const float* enc_out = (const float*)d_in[0];
    const int*   caps    = (const int*)  d_in[1];
    const int*   caplen  = (const int*)  d_in[2];
    const float* emb     = (const float*)d_in[3];
    const float* eaW     = (const float*)d_in[4];
    const float* eab     = (const float*)d_in[5];
    const float* daW     = (const float*)d_in[6];
    const float* dab     = (const float*)d_in[7];
    const float* faW     = (const float*)d_in[8];
    const float* fab     = (const float*)d_in[9];
    const float* fbW     = (const float*)d_in[10];
    const float* fbb     = (const float*)d_in[11];
    const float* l1Wih   = (const float*)d_in[12];
    const float* l1Whh   = (const float*)d_in[13];
    const float* l1bih   = (const float*)d_in[14];
    const float* l1bhh   = (const float*)d_in[15];
    const float* l2Wih   = (const float*)d_in[16];
    const float* l2Whh   = (const float*)d_in[17];
    const float* l2bih   = (const float*)d_in[18];
    const float* l2bhh   = (const float*)d_in[19];
    const float* ramW    = (const float*)d_in[20];
    const float* ramb    = (const float*)d_in[21];
    const float* rpmW    = (const float*)d_in[22];
    float* out = (float*)d_out;

    // device symbol addresses (device-side linkage; host uses kernels only)
    float* p_encs;  cudaGetSymbolAddress((void**)&p_encs,  d_encs);
    float* p_att1;  cudaGetSymbolAddress((void**)&p_att1,  d_att1);
    float* p_econ;  cudaGetSymbolAddress((void**)&p_econ,  d_econ);
    float* p_embg;  cudaGetSymbolAddress((void**)&p_embg,  d_embg);
    float* p_W1;    cudaGetSymbolAddress((void**)&p_W1,    d_W1cat);
    float* p_W2;    cudaGetSymbolAddress((void**)&p_W2,    d_W2cat);
    float* p_W3;    cudaGetSymbolAddress((void**)&p_W3,    d_W3cat);
    float* p_b1;    cudaGetSymbolAddress((void**)&p_b1,    d_b1sum);
    float* p_b2;    cudaGetSymbolAddress((void**)&p_b2,    d_b2sum);
    float* p_b3;    cudaGetSymbolAddress((void**)&p_b3,    d_b3cat);
    float* p_base1; cudaGetSymbolAddress((void**)&p_base1, d_base1);
    float* p_gates; cudaGetSymbolAddress((void**)&p_gates, d_gates);
    float* p_x1;    cudaGetSymbolAddress((void**)&p_x1,    d_x1);
    float* p_x2;    cudaGetSymbolAddress((void**)&p_x2,    d_x2);
    float* p_ag;    cudaGetSymbolAddress((void**)&p_ag,    d_ag);
    float* p_mean;  cudaGetSymbolAddress((void**)&p_mean,  d_mean);
    float* p_h2;    cudaGetSymbolAddress((void**)&p_h2,    d_h2all);

    // 1. sort / small outputs / tokens
    setup_kernel<<<1, BBS>>>(caplen, caps, out);

    // 2. gather sorted encoder (12,845,056 float4)
    gather_enc_kernel<<<50176, 256>>>(enc_out);

    // 3. mean over pixels
    mean_kernel<<<(BBS * ENCD) / 256, 256>>>();

    // 4. weight concatenations + bias sums
    bias_kernel<<<4096 / 256, 256>>>(l1bih, l1bhh, l2bih, l2bhh, dab, fbb);
    w1copy_kernel<<<(4096 * 2048 / 4) / 256, 256>>>(l1Wih, l1Whh);
    w2copy_kernel<<<(4096 * 4096 / 4) / 256, 256>>>(l2Wih, l2Whh);
    w3copy_kernel<<<(3072 * 1024 / 4) / 256, 256>>>(daW, fbW);

    // 5. token embedding gather
    embg_kernel<<<TTS * BBS, 256>>>(emb);

    // 6. base1 = mean_enc @ Wih[:,2048:].T + (bih+bhh)   (128 x 4096, K=2048)
    gemm_tn<32, 64, 2, 4, true, 0, false><<<dim3(4096 / 64, BBS / 32), 256>>>(
        p_mean, l1Wih + 2048, p_b1, nullptr, nullptr, p_base1,
        4096, 2048, 2048, 4096, 4096);

    // 7. econ = embg @ Wih[:,0:1024].T   (2688 x 4096, K=1024)
    gemm_tn<64, 64, 4, 4, false, 0, false><<<dim3(4096 / 64, (TTS * BBS) / 64), 256>>>(
        p_embg, l1Wih, nullptr, nullptr, nullptr, p_econ,
        4096, 1024, 1024, 4096, 4096);

    // 8. att1 = enc_sorted @ enc_att_W.T + b   (25088 x 1024, K=2048)
    gemm_tn<64, 64, 4, 4, true, 0, false><<<dim3(1024 / 64, (BBS * PPS) / 64), 256>>>(
        p_encs, eaW, eab, nullptr, nullptr, p_att1,
        1024, 2048, 2048, 2048, 1024);

    // 9. zero states
    zero_kernel<<<(BBS * 4096) / 256, 256>>>();

    // 10. sequential decode
    for (int t = 0; t < TTS; ++t) {
        // gates1 = [h2|h1] @ W1cat.T + base1 + econ[t]
        gemm_tn<32, 64, 2, 4, false, 2, false><<<dim3(4096 / 64, BBS / 32), 256>>>(
            p_x1, p_W1, nullptr, p_base1, p_econ + (size_t)t * BBS * 4096,
            p_gates, 4096, 2048, 2048, 2048, 4096);

        lstm1_kernel<<<(BBS * DHID) / 256, 256>>>(t);

        // [att2 | gate logits] = h1n @ [dec_att_W ; f_beta_W].T + b3
        gemm_tn<32, 64, 2, 4, true, 0, false><<<dim3(3072 / 64, BBS / 32), 256>>>(
            p_x2 + 2048, p_W3, p_b3, nullptr, nullptr, p_ag,
            3072, 1024, 4096, 1024, 3072);

        attn_kernel<<<BBS, 256>>>(faW, fab);

        // gates2 = [att|h1n|h2] @ [l2_Wih|l2_Whh].T + (bih+bhh)
        gemm_tn<32, 64, 2, 4, true, 0, false><<<dim3(4096 / 64, BBS / 32), 256>>>(
            p_x2, p_W2, p_b2, nullptr, nullptr, p_gates,
            4096, 4096, 4096, 4096, 4096);

        lstm2_kernel<<<(BBS * DHID) / 256, 256>>>(t);
    }

    // 11. predictions = h2all @ ram_W.T + ram_b, permuted + masked store
    gemm_tn<64, 64, 4, 4, true, 0, true><<<dim3(VOC / 64, (TTS * BBS) / 64), 256>>>(
        p_h2, ramW, ramb, nullptr, nullptr, out + O_PRED,
        VOC, 1024, 1024, 1024, VOC);

    // 12. predicted_pos
    rpm_kernel<<<(TTS * BBS + 7) / 8, 256>>>(rpmW, out);
}